// round 7
// baseline (speedup 1.0000x reference)
#include <cuda_runtime.h>
#include <cuda_bf16.h>
#include <math.h>
#include <stdint.h>

#define S_LEN  2048
#define BATCH  2
#define DMODEL 4096
#define NH     32
#define NKV    8
#define HDIM   128
#define MROWS  (BATCH * S_LEN)   // 4096

// ---------------- scratch (__device__ globals; no allocs allowed) ----------
__device__ __align__(16) float g_q[(size_t)MROWS * NH * HDIM];
__device__ __align__(16) float g_k[(size_t)MROWS * NKV * HDIM];
__device__ __align__(16) float g_v[(size_t)MROWS * NKV * HDIM];

__device__ __align__(16) __nv_bfloat16 g_xh[(size_t)MROWS * DMODEL];   // reused as q_hi
__device__ __align__(16) __nv_bfloat16 g_xl[(size_t)MROWS * DMODEL];   // reused as q_lo
__device__ __align__(16) __nv_bfloat16 g_kh[(size_t)MROWS * NKV * HDIM];
__device__ __align__(16) __nv_bfloat16 g_kl[(size_t)MROWS * NKV * HDIM];
__device__ __align__(16) __nv_bfloat16 g_vh[(size_t)MROWS * NKV * HDIM];
__device__ __align__(16) __nv_bfloat16 g_vl[(size_t)MROWS * NKV * HDIM];
__device__ __align__(16) __nv_bfloat16 g_wqt_h[(size_t)DMODEL * DMODEL];
__device__ __align__(16) __nv_bfloat16 g_wqt_l[(size_t)DMODEL * DMODEL];
__device__ __align__(16) __nv_bfloat16 g_wkt_h[(size_t)(NKV*HDIM) * DMODEL];
__device__ __align__(16) __nv_bfloat16 g_wkt_l[(size_t)(NKV*HDIM) * DMODEL];
__device__ __align__(16) __nv_bfloat16 g_wvt_h[(size_t)(NKV*HDIM) * DMODEL];
__device__ __align__(16) __nv_bfloat16 g_wvt_l[(size_t)(NKV*HDIM) * DMODEL];
__device__ __align__(16) __nv_bfloat16 g_wot_h[(size_t)DMODEL * DMODEL];
__device__ __align__(16) __nv_bfloat16 g_wot_l[(size_t)DMODEL * DMODEL];
__device__ __align__(16) __nv_bfloat16 g_oh[(size_t)MROWS * DMODEL];
__device__ __align__(16) __nv_bfloat16 g_ol[(size_t)MROWS * DMODEL];

// ---------------- helpers ---------------------------------------------------
__device__ __forceinline__ uint32_t smem_u32(const void* p) {
    return (uint32_t)__cvta_generic_to_shared(p);
}
__device__ __forceinline__ void cp16(uint32_t dst, const void* src) {
    asm volatile("cp.async.ca.shared.global [%0], [%1], 16;" :: "r"(dst), "l"(src) : "memory");
}
__device__ __forceinline__ void cp_commit() {
    asm volatile("cp.async.commit_group;" ::: "memory");
}
__device__ __forceinline__ void ldsm4(uint32_t& r0, uint32_t& r1, uint32_t& r2, uint32_t& r3,
                                      uint32_t addr) {
    asm volatile("ldmatrix.sync.aligned.m8n8.x4.shared.b16 {%0,%1,%2,%3}, [%4];"
                 : "=r"(r0), "=r"(r1), "=r"(r2), "=r"(r3) : "r"(addr));
}
__device__ __forceinline__ void ldsm4t(uint32_t& r0, uint32_t& r1, uint32_t& r2, uint32_t& r3,
                                       uint32_t addr) {
    asm volatile("ldmatrix.sync.aligned.m8n8.x4.trans.shared.b16 {%0,%1,%2,%3}, [%4];"
                 : "=r"(r0), "=r"(r1), "=r"(r2), "=r"(r3) : "r"(addr));
}
__device__ __forceinline__ void mma_bf16(float* d, const uint32_t* a, const uint32_t* b) {
    asm volatile("mma.sync.aligned.m16n8k16.row.col.f32.bf16.bf16.f32 "
                 "{%0,%1,%2,%3}, {%4,%5,%6,%7}, {%8,%9}, {%0,%1,%2,%3};"
                 : "+f"(d[0]), "+f"(d[1]), "+f"(d[2]), "+f"(d[3])
                 : "r"(a[0]), "r"(a[1]), "r"(a[2]), "r"(a[3]), "r"(b[0]), "r"(b[1]));
}
__device__ __forceinline__ uint32_t packbf(float lo, float hi) {
    uint32_t r;
    asm("cvt.rn.bf16x2.f32 %0, %1, %2;" : "=r"(r) : "f"(hi), "f"(lo));
    return r;
}

// ---------------------------------------------------------------------------
// fp32 -> (hi, lo) bf16 split, elementwise
// ---------------------------------------------------------------------------
__global__ void split4_kernel(const float* __restrict__ in,
                              __nv_bfloat16* __restrict__ h,
                              __nv_bfloat16* __restrict__ l, int n4)
{
    int i = blockIdx.x * blockDim.x + threadIdx.x;
    if (i >= n4) return;
    float4 x = ((const float4*)in)[i];
    __nv_bfloat16 h0 = __float2bfloat16(x.x), h1 = __float2bfloat16(x.y);
    __nv_bfloat16 h2 = __float2bfloat16(x.z), h3 = __float2bfloat16(x.w);
    __nv_bfloat16 l0 = __float2bfloat16(x.x - __bfloat162float(h0));
    __nv_bfloat16 l1 = __float2bfloat16(x.y - __bfloat162float(h1));
    __nv_bfloat16 l2 = __float2bfloat16(x.z - __bfloat162float(h2));
    __nv_bfloat16 l3 = __float2bfloat16(x.w - __bfloat162float(h3));
    ((__nv_bfloat162*)h)[2*i]   = __nv_bfloat162(h0, h1);
    ((__nv_bfloat162*)h)[2*i+1] = __nv_bfloat162(h2, h3);
    ((__nv_bfloat162*)l)[2*i]   = __nv_bfloat162(l0, l1);
    ((__nv_bfloat162*)l)[2*i+1] = __nv_bfloat162(l2, l3);
}

// ---------------------------------------------------------------------------
// RoPE + split: rotate fp32 pairs, emit bf16 hi/lo
// ---------------------------------------------------------------------------
__global__ void rope_split_kernel(const float* __restrict__ src,
                                  const float* __restrict__ cs, const float* __restrict__ sn,
                                  __nv_bfloat16* __restrict__ dh, __nv_bfloat16* __restrict__ dl,
                                  int nheads, int total)
{
    int idx = blockIdx.x * blockDim.x + threadIdx.x;
    if (idx >= total) return;
    int p    = idx & 63;
    int rest = idx >> 6;
    int s    = (rest / nheads) & (S_LEN - 1);
    float c  = cs[s * 64 + p];
    float sv = sn[s * 64 + p];
    size_t off = (size_t)rest * HDIM + 2 * p;
    float2 x = *(const float2*)&src[off];
    float o0 = x.x * c  - x.y * sv;
    float o1 = x.x * sv + x.y * c;
    __nv_bfloat16 h0 = __float2bfloat16(o0), h1 = __float2bfloat16(o1);
    *(__nv_bfloat162*)&dh[off] = __nv_bfloat162(h0, h1);
    *(__nv_bfloat162*)&dl[off] = __nv_bfloat162(
        __float2bfloat16(o0 - __bfloat162float(h0)),
        __float2bfloat16(o1 - __bfloat162float(h1)));
}

// ---------------------------------------------------------------------------
// W[K,N] fp32 -> WT[N,K] (hi, lo) bf16, tiled transpose
// ---------------------------------------------------------------------------
__global__ void split_transpose_kernel(const float* __restrict__ W,
                                       __nv_bfloat16* __restrict__ Th,
                                       __nv_bfloat16* __restrict__ Tl,
                                       int K, int N)
{
    __shared__ float t[32][33];
    int k0 = blockIdx.y * 32, n0 = blockIdx.x * 32;
    int x = threadIdx.x, y = threadIdx.y;
#pragma unroll
    for (int j = 0; j < 32; j += 8)
        t[y + j][x] = W[(size_t)(k0 + y + j) * N + n0 + x];
    __syncthreads();
#pragma unroll
    for (int j = 0; j < 32; j += 8) {
        float v = t[x][y + j];
        __nv_bfloat16 h = __float2bfloat16(v);
        __nv_bfloat16 l = __float2bfloat16(v - __bfloat162float(h));
        size_t off = (size_t)(n0 + y + j) * K + k0 + x;
        Th[off] = h;
        Tl[off] = l;
    }
}

// ---------------------------------------------------------------------------
// mma.sync bf16 3-pass GEMM v2: C[M,Ndim] = A[M,K] @ Bt[Ndim,K]^T
// CTA 128x256, BK=32, 8 warps (2x4), warp tile 64x64, cp.async double buffer.
// smem pitch 40 halves (80B) -> conflict-free ldmatrix.
// ---------------------------------------------------------------------------
#define PITCH_B 80                    // bytes per k-row (32 halves + 8 pad)
#define ARR_A (128 * PITCH_B)         // 10240 B
#define ARR_BB (256 * PITCH_B)        // 20480 B
#define OFF_AH 0
#define OFF_AL ARR_A
#define OFF_BH (2 * ARR_A)
#define OFF_BL (2 * ARR_A + ARR_BB)
#define STAGE_B (2 * ARR_A + 2 * ARR_BB)   // 61440
#define GEMM_SMEM (2 * STAGE_B)            // 122880

__global__ __launch_bounds__(256) void gemm_mma_bf16x3(
    const __nv_bfloat16* __restrict__ Ah_, const __nv_bfloat16* __restrict__ Al_,
    const __nv_bfloat16* __restrict__ Bh_, const __nv_bfloat16* __restrict__ Bl_,
    float* __restrict__ C, int Ndim, int Kdim)
{
    extern __shared__ __align__(16) char sm[];
    const uint32_t sbase = smem_u32(sm);
    const int tid  = threadIdx.x;
    const int lane = tid & 31;
    const int wid  = tid >> 5;
    const int wm   = wid >> 2;      // 0..1
    const int wn   = wid & 3;       // 0..3
    const int row0 = blockIdx.y * 128;
    const int col0 = blockIdx.x * 256;

    // per-thread cp.async source/dest lists (12 x 16B per stage)
    const __nv_bfloat16* gsrc[12];
    uint32_t sdst[12];
#pragma unroll
    for (int j = 0; j < 2; j++) {                 // A: 128 rows x 4 chunks
        int v = tid + 256 * j;
        int row = v >> 2, c16 = v & 3;
        size_t ga = (size_t)(row0 + row) * Kdim + c16 * 8;
        uint32_t so = (uint32_t)row * PITCH_B + c16 * 16;
        gsrc[j*2+0] = Ah_ + ga;  sdst[j*2+0] = OFF_AH + so;
        gsrc[j*2+1] = Al_ + ga;  sdst[j*2+1] = OFF_AL + so;
    }
#pragma unroll
    for (int j = 0; j < 4; j++) {                 // B: 256 rows x 4 chunks
        int v = tid + 256 * j;
        int row = v >> 2, c16 = v & 3;
        size_t gb = (size_t)(col0 + row) * Kdim + c16 * 8;
        uint32_t so = (uint32_t)row * PITCH_B + c16 * 16;
        gsrc[4+j*2+0] = Bh_ + gb;  sdst[4+j*2+0] = OFF_BH + so;
        gsrc[4+j*2+1] = Bl_ + gb;  sdst[4+j*2+1] = OFF_BL + so;
    }

    const uint32_t aoff = (uint32_t)(wm * 64 + (lane & 15)) * PITCH_B + (lane >> 4) * 16;
    const uint32_t boff = (uint32_t)(wn * 64 + (lane >> 4) * 8 + (lane & 7)) * PITCH_B
                          + ((lane >> 3) & 1) * 16;

    float acc[4][8][4];
#pragma unroll
    for (int mt = 0; mt < 4; mt++)
#pragma unroll
        for (int nt = 0; nt < 8; nt++)
#pragma unroll
            for (int r = 0; r < 4; r++) acc[mt][nt][r] = 0.0f;

    const int NC = Kdim / 32;

#pragma unroll
    for (int t = 0; t < 12; t++) cp16(sbase + sdst[t], gsrc[t]);
    cp_commit();

    for (int i = 0; i < NC; i++) {
        if (i + 1 < NC) {
            const uint32_t nb = sbase + ((i + 1) & 1) * STAGE_B;
#pragma unroll
            for (int t = 0; t < 12; t++) cp16(nb + sdst[t], gsrc[t] + (size_t)(i + 1) * 32);
            cp_commit();
            asm volatile("cp.async.wait_group 1;" ::: "memory");
        } else {
            asm volatile("cp.async.wait_group 0;" ::: "memory");
        }
        __syncthreads();

        const uint32_t st = sbase + (i & 1) * STAGE_B;
#pragma unroll
        for (int ks = 0; ks < 2; ks++) {
            const uint32_t kb = ks * 32;
            uint32_t ah[4][4], al[4][4];
#pragma unroll
            for (int mt = 0; mt < 4; mt++) {
                ldsm4(ah[mt][0], ah[mt][1], ah[mt][2], ah[mt][3],
                      st + OFF_AH + aoff + mt * 16 * PITCH_B + kb);
                ldsm4(al[mt][0], al[mt][1], al[mt][2], al[mt][3],
                      st + OFF_AL + aoff + mt * 16 * PITCH_B + kb);
            }
#pragma unroll
            for (int np = 0; np < 4; np++) {
                uint32_t bh[2][2], bl[2][2];
                uint32_t adr = st + OFF_BH + boff + np * 16 * PITCH_B + kb;
                ldsm4(bh[0][0], bh[0][1], bh[1][0], bh[1][1], adr);
                ldsm4(bl[0][0], bl[0][1], bl[1][0], bl[1][1], adr + (OFF_BL - OFF_BH));
#pragma unroll
                for (int t = 0; t < 2; t++) {
                    const int nt = np * 2 + t;
#pragma unroll
                    for (int mt = 0; mt < 4; mt++) {
                        mma_bf16(acc[mt][nt], ah[mt], bh[t]);
                        mma_bf16(acc[mt][nt], ah[mt], bl[t]);
                        mma_bf16(acc[mt][nt], al[mt], bh[t]);
                    }
                }
            }
        }
        __syncthreads();
    }

    // epilogue
#pragma unroll
    for (int mt = 0; mt < 4; mt++) {
        int r = row0 + wm * 64 + mt * 16 + (lane >> 2);
#pragma unroll
        for (int nt = 0; nt < 8; nt++) {
            int c = col0 + wn * 64 + nt * 8 + (lane & 3) * 2;
            *(float2*)&C[(size_t)r * Ndim + c]       = make_float2(acc[mt][nt][0], acc[mt][nt][1]);
            *(float2*)&C[(size_t)(r + 8) * Ndim + c] = make_float2(acc[mt][nt][2], acc[mt][nt][3]);
        }
    }
}

// ---------------------------------------------------------------------------
// Tensor-core causal flash attention (unchanged, known-good)
// ---------------------------------------------------------------------------
#define FBR 64
#define FBC 64
#define FP  136
#define FAB (FBR * FP)
#define FLASH2_SMEM (6 * FAB * 2)

__global__ __launch_bounds__(128) void flash_tc(
    const __nv_bfloat16* __restrict__ Qh_, const __nv_bfloat16* __restrict__ Ql_,
    const __nv_bfloat16* __restrict__ Kh_, const __nv_bfloat16* __restrict__ Kl_,
    const __nv_bfloat16* __restrict__ Vh_, const __nv_bfloat16* __restrict__ Vl_,
    __nv_bfloat16* __restrict__ Oh_, __nv_bfloat16* __restrict__ Ol_)
{
    extern __shared__ __align__(16) __nv_bfloat16 smh[];
    const int tid  = threadIdx.x;
    const int lane = tid & 31;
    const int w    = tid >> 5;
    const int qt   = gridDim.x - 1 - blockIdx.x;
    const int h    = blockIdx.y;
    const int b    = blockIdx.z;
    const int g    = h >> 2;
    const int q0   = qt * FBR;

    const uint32_t sb = smem_u32(smh);
    const uint32_t oQh = 0, oQl = FAB*2, oKh = 4*FAB, oVh = 8*FAB;

    for (int i = tid; i < FBR * 16; i += 128) {
        int r = i >> 4, c = i & 15;
        size_t gq = ((size_t)((b*S_LEN + q0 + r) * NH) + h) * HDIM + c * 8;
        *(uint4*)&smh[r*FP + c*8]        = *(const uint4*)&Qh_[gq];
        *(uint4*)&smh[FAB + r*FP + c*8]  = *(const uint4*)&Ql_[gq];
    }

    const uint32_t aoff = ((uint32_t)(w*16 + (lane & 15)) * FP) * 2 + (lane >> 4) * 16;
    const uint32_t boff = ((uint32_t)((lane >> 4) * 8 + (lane & 7)) * FP) * 2 + ((lane >> 3) & 1) * 16;
    const uint32_t voff = ((uint32_t)(((lane >> 3) & 1) * 8 + (lane & 7)) * FP) * 2 + (lane >> 4) * 16;

    float oacc[16][4];
#pragma unroll
    for (int t = 0; t < 16; t++)
#pragma unroll
        for (int r = 0; r < 4; r++) oacc[t][r] = 0.0f;
    float m0 = -3.0e38f, m1 = -3.0e38f, l0 = 0.0f, l1 = 0.0f;

    const float scale = 0.08838834764831845f;

    for (int jt = 0; jt <= qt; jt++) {
        const int j0 = jt * FBC;
        __syncthreads();
        for (int i = tid; i < FBC * 16; i += 128) {
            int r = i >> 4, c = i & 15;
            size_t gk = ((size_t)((b*S_LEN + j0 + r) * NKV) + g) * HDIM + c * 8;
            *(uint4*)&smh[2*FAB + r*FP + c*8] = *(const uint4*)&Kh_[gk];
            *(uint4*)&smh[3*FAB + r*FP + c*8] = *(const uint4*)&Kl_[gk];
            *(uint4*)&smh[4*FAB + r*FP + c*8] = *(const uint4*)&Vh_[gk];
            *(uint4*)&smh[5*FAB + r*FP + c*8] = *(const uint4*)&Vl_[gk];
        }
        __syncthreads();

        float sv[8][4];
#pragma unroll
        for (int t = 0; t < 8; t++)
#pragma unroll
            for (int r = 0; r < 4; r++) sv[t][r] = 0.0f;

#pragma unroll
        for (int ks = 0; ks < 8; ks++) {
            uint32_t ah[4], al[4], bh[8][2], bl[8][2];
            ldsm4(ah[0], ah[1], ah[2], ah[3], sb + oQh + aoff + ks*32);
            ldsm4(al[0], al[1], al[2], al[3], sb + oQl + aoff + ks*32);
#pragma unroll
            for (int nn = 0; nn < 4; nn++) {
                uint32_t adr = sb + oKh + boff + nn * (16*FP*2) + ks*32;
                ldsm4(bh[2*nn][0], bh[2*nn][1], bh[2*nn+1][0], bh[2*nn+1][1], adr);
                ldsm4(bl[2*nn][0], bl[2*nn][1], bl[2*nn+1][0], bl[2*nn+1][1], adr + 2*FAB);
            }
#pragma unroll
            for (int t = 0; t < 8; t++) {
                mma_bf16(sv[t], ah, bh[t]);
                mma_bf16(sv[t], ah, bl[t]);
                mma_bf16(sv[t], al, bh[t]);
            }
        }

#pragma unroll
        for (int t = 0; t < 8; t++) {
            sv[t][0] *= scale; sv[t][1] *= scale;
            sv[t][2] *= scale; sv[t][3] *= scale;
        }
        if (jt == qt) {
            int row = q0 + w*16 + (lane >> 2);
            int cb  = j0 + (lane & 3) * 2;
#pragma unroll
            for (int t = 0; t < 8; t++) {
                int c0 = cb + t*8;
                if (c0     > row    ) sv[t][0] = -1.0e30f;
                if (c0 + 1 > row    ) sv[t][1] = -1.0e30f;
                if (c0     > row + 8) sv[t][2] = -1.0e30f;
                if (c0 + 1 > row + 8) sv[t][3] = -1.0e30f;
            }
        }

        float mx0 = -1.0e30f, mx1 = -1.0e30f;
#pragma unroll
        for (int t = 0; t < 8; t++) {
            mx0 = fmaxf(mx0, fmaxf(sv[t][0], sv[t][1]));
            mx1 = fmaxf(mx1, fmaxf(sv[t][2], sv[t][3]));
        }
        mx0 = fmaxf(mx0, __shfl_xor_sync(0xffffffffu, mx0, 1));
        mx0 = fmaxf(mx0, __shfl_xor_sync(0xffffffffu, mx0, 2));
        mx1 = fmaxf(mx1, __shfl_xor_sync(0xffffffffu, mx1, 1));
        mx1 = fmaxf(mx1, __shfl_xor_sync(0xffffffffu, mx1, 2));
        float mnew0 = fmaxf(m0, mx0), mnew1 = fmaxf(m1, mx1);
        float corr0 = __expf(m0 - mnew0), corr1 = __expf(m1 - mnew1);

        float rl0 = 0.0f, rl1 = 0.0f;
        uint32_t paH[4][4], paL[4][4];
#pragma unroll
        for (int u = 0; u < 4; u++) {
            float p00 = __expf(sv[2*u][0]   - mnew0), p01 = __expf(sv[2*u][1]   - mnew0);
            float p02 = __expf(sv[2*u][2]   - mnew1), p03 = __expf(sv[2*u][3]   - mnew1);
            float p10 = __expf(sv[2*u+1][0] - mnew0), p11 = __expf(sv[2*u+1][1] - mnew0);
            float p12 = __expf(sv[2*u+1][2] - mnew1), p13 = __expf(sv[2*u+1][3] - mnew1);
            rl0 += p00 + p01 + p10 + p11;
            rl1 += p02 + p03 + p12 + p13;
            paH[u][0] = packbf(p00, p01);
            paH[u][1] = packbf(p02, p03);
            paH[u][2] = packbf(p10, p11);
            paH[u][3] = packbf(p12, p13);
            float q00 = p00 - __bfloat162float(__float2bfloat16(p00));
            float q01 = p01 - __bfloat162float(__float2bfloat16(p01));
            float q02 = p02 - __bfloat162float(__float2bfloat16(p02));
            float q03 = p03 - __bfloat162float(__float2bfloat16(p03));
            float q10 = p10 - __bfloat162float(__float2bfloat16(p10));
            float q11 = p11 - __bfloat162float(__float2bfloat16(p11));
            float q12 = p12 - __bfloat162float(__float2bfloat16(p12));
            float q13 = p13 - __bfloat162float(__float2bfloat16(p13));
            paL[u][0] = packbf(q00, q01);
            paL[u][1] = packbf(q02, q03);
            paL[u][2] = packbf(q10, q11);
            paL[u][3] = packbf(q12, q13);
        }
        rl0 += __shfl_xor_sync(0xffffffffu, rl0, 1);
        rl0 += __shfl_xor_sync(0xffffffffu, rl0, 2);
        rl1 += __shfl_xor_sync(0xffffffffu, rl1, 1);
        rl1 += __shfl_xor_sync(0xffffffffu, rl1, 2);
        l0 = l0 * corr0 + rl0;
        l1 = l1 * corr1 + rl1;
        m0 = mnew0; m1 = mnew1;
#pragma unroll
        for (int t = 0; t < 16; t++) {
            oacc[t][0] *= corr0; oacc[t][1] *= corr0;
            oacc[t][2] *= corr1; oacc[t][3] *= corr1;
        }

#pragma unroll
        for (int u = 0; u < 4; u++) {
#pragma unroll
            for (int dh2 = 0; dh2 < 2; dh2++) {
                uint32_t bvh[8][2], bvl[8][2];
#pragma unroll
                for (int dd = 0; dd < 4; dd++) {
                    uint32_t adr = sb + oVh + voff + u * (16*FP*2) + (dh2*64 + dd*16) * 2;
                    ldsm4t(bvh[2*dd][0], bvh[2*dd][1], bvh[2*dd+1][0], bvh[2*dd+1][1], adr);
                    ldsm4t(bvl[2*dd][0], bvl[2*dd][1], bvl[2*dd+1][0], bvl[2*dd+1][1], adr + 2*FAB);
                }
#pragma unroll
                for (int t = 0; t < 8; t++) {
                    mma_bf16(oacc[dh2*8+t], paH[u], bvh[t]);
                    mma_bf16(oacc[dh2*8+t], paH[u], bvl[t]);
                    mma_bf16(oacc[dh2*8+t], paL[u], bvh[t]);
                }
            }
        }
    }

    float inv0 = 1.0f / l0, inv1 = 1.0f / l1;
    int rowa = b*S_LEN + q0 + w*16 + (lane >> 2);
    size_t base0 = ((size_t)rowa * NH + h) * HDIM;
    size_t base1 = base0 + (size_t)8 * NH * HDIM;
#pragma unroll
    for (int t = 0; t < 16; t++) {
        int c = t*8 + (lane & 3) * 2;
        float v0 = oacc[t][0] * inv0, v1 = oacc[t][1] * inv0;
        float v2 = oacc[t][2] * inv1, v3 = oacc[t][3] * inv1;
        __nv_bfloat16 h0 = __float2bfloat16(v0), h1 = __float2bfloat16(v1);
        __nv_bfloat16 h2 = __float2bfloat16(v2), h3 = __float2bfloat16(v3);
        *(__nv_bfloat162*)&Oh_[base0 + c] = __nv_bfloat162(h0, h1);
        *(__nv_bfloat162*)&Oh_[base1 + c] = __nv_bfloat162(h2, h3);
        *(__nv_bfloat162*)&Ol_[base0 + c] = __nv_bfloat162(
            __float2bfloat16(v0 - __bfloat162float(h0)),
            __float2bfloat16(v1 - __bfloat162float(h1)));
        *(__nv_bfloat162*)&Ol_[base1 + c] = __nv_bfloat162(
            __float2bfloat16(v2 - __bfloat162float(h2)),
            __float2bfloat16(v3 - __bfloat162float(h3)));
    }
}

// ---------------------------------------------------------------------------
// Launch
// ---------------------------------------------------------------------------
extern "C" void kernel_launch(void* const* d_in, const int* in_sizes, int n_in,
                              void* d_out, int out_size)
{
    const float* x  = (const float*)d_in[0];
    const float* wq = (const float*)d_in[1];
    const float* wk = (const float*)d_in[2];
    const float* wv = (const float*)d_in[3];
    const float* wo = (const float*)d_in[4];
    const float* fc = (const float*)d_in[5];
    const float* fs = (const float*)d_in[6];
    float* out = (float*)d_out;

    float *q, *k, *v;
    cudaGetSymbolAddress((void**)&q, g_q);
    cudaGetSymbolAddress((void**)&k, g_k);
    cudaGetSymbolAddress((void**)&v, g_v);
    __nv_bfloat16 *xh, *xl, *kh, *kl, *vh, *vl;
    __nv_bfloat16 *wqth, *wqtl, *wkth, *wktl, *wvth, *wvtl, *woth, *wotl, *oh, *ol;
    cudaGetSymbolAddress((void**)&xh, g_xh);      cudaGetSymbolAddress((void**)&xl, g_xl);
    cudaGetSymbolAddress((void**)&kh, g_kh);      cudaGetSymbolAddress((void**)&kl, g_kl);
    cudaGetSymbolAddress((void**)&vh, g_vh);      cudaGetSymbolAddress((void**)&vl, g_vl);
    cudaGetSymbolAddress((void**)&wqth, g_wqt_h); cudaGetSymbolAddress((void**)&wqtl, g_wqt_l);
    cudaGetSymbolAddress((void**)&wkth, g_wkt_h); cudaGetSymbolAddress((void**)&wktl, g_wkt_l);
    cudaGetSymbolAddress((void**)&wvth, g_wvt_h); cudaGetSymbolAddress((void**)&wvtl, g_wvt_l);
    cudaGetSymbolAddress((void**)&woth, g_wot_h); cudaGetSymbolAddress((void**)&wotl, g_wot_l);
    cudaGetSymbolAddress((void**)&oh, g_oh);      cudaGetSymbolAddress((void**)&ol, g_ol);

    // split inputs / weights into bf16 hi/lo
    int n4 = (MROWS * DMODEL) / 4;
    split4_kernel<<<(n4 + 255) / 256, 256>>>(x, xh, xl, n4);
    split_transpose_kernel<<<dim3(DMODEL / 32, DMODEL / 32), dim3(32, 8)>>>(wq, wqth, wqtl, DMODEL, DMODEL);
    split_transpose_kernel<<<dim3((NKV * HDIM) / 32, DMODEL / 32), dim3(32, 8)>>>(wk, wkth, wktl, DMODEL, NKV * HDIM);
    split_transpose_kernel<<<dim3((NKV * HDIM) / 32, DMODEL / 32), dim3(32, 8)>>>(wv, wvth, wvtl, DMODEL, NKV * HDIM);
    split_transpose_kernel<<<dim3(DMODEL / 32, DMODEL / 32), dim3(32, 8)>>>(wo, woth, wotl, DMODEL, DMODEL);

    cudaFuncSetAttribute(gemm_mma_bf16x3, cudaFuncAttributeMaxDynamicSharedMemorySize, GEMM_SMEM);

    // QKV projections
    gemm_mma_bf16x3<<<dim3((NH * HDIM) / 256,  MROWS / 128), 256, GEMM_SMEM>>>(xh, xl, wqth, wqtl, q, NH * HDIM,  DMODEL);
    gemm_mma_bf16x3<<<dim3((NKV * HDIM) / 256, MROWS / 128), 256, GEMM_SMEM>>>(xh, xl, wkth, wktl, k, NKV * HDIM, DMODEL);
    gemm_mma_bf16x3<<<dim3((NKV * HDIM) / 256, MROWS / 128), 256, GEMM_SMEM>>>(xh, xl, wvth, wvtl, v, NKV * HDIM, DMODEL);

    // RoPE + bf16 split (q reuses xh/xl — safe, GEMMs above already consumed them)
    int qtot = MROWS * NH  * 64;
    int ktot = MROWS * NKV * 64;
    rope_split_kernel<<<(qtot + 255) / 256, 256>>>(q, fc, fs, xh, xl, NH,  qtot);
    rope_split_kernel<<<(ktot + 255) / 256, 256>>>(k, fc, fs, kh, kl, NKV, ktot);
    int v4 = (MROWS * NKV * HDIM) / 4;
    split4_kernel<<<(v4 + 255) / 256, 256>>>(v, vh, vl, v4);

    // Tensor-core flash attention -> bf16 hi/lo output
    cudaFuncSetAttribute(flash_tc, cudaFuncAttributeMaxDynamicSharedMemorySize, FLASH2_SMEM);
    flash_tc<<<dim3(S_LEN / FBR, NH, BATCH), 128, FLASH2_SMEM>>>(xh, xl, kh, kl, vh, vl, oh, ol);

    // Output projection
    gemm_mma_bf16x3<<<dim3(DMODEL / 256, MROWS / 128), 256, GEMM_SMEM>>>(oh, ol, woth, wotl, out, DMODEL, DMODEL);
}

// round 9
// speedup vs baseline: 1.0760x; 1.0760x over previous
#include <cuda_runtime.h>
#include <cuda_bf16.h>
#include <math.h>
#include <stdint.h>

#define S_LEN  2048
#define BATCH  2
#define DMODEL 4096
#define NH     32
#define NKV    8
#define HDIM   128
#define MROWS  (BATCH * S_LEN)   // 4096

// ---------------- scratch (__device__ globals; no allocs allowed) ----------
__device__ __align__(16) float g_q[(size_t)MROWS * NH * HDIM];
__device__ __align__(16) float g_k[(size_t)MROWS * NKV * HDIM];
__device__ __align__(16) float g_v[(size_t)MROWS * NKV * HDIM];

__device__ __align__(16) __nv_bfloat16 g_xh[(size_t)MROWS * DMODEL];   // reused as q_hi
__device__ __align__(16) __nv_bfloat16 g_xl[(size_t)MROWS * DMODEL];   // reused as q_lo
__device__ __align__(16) __nv_bfloat16 g_kh[(size_t)MROWS * NKV * HDIM];
__device__ __align__(16) __nv_bfloat16 g_kl[(size_t)MROWS * NKV * HDIM];
__device__ __align__(16) __nv_bfloat16 g_vh[(size_t)MROWS * NKV * HDIM];
__device__ __align__(16) __nv_bfloat16 g_vl[(size_t)MROWS * NKV * HDIM];
__device__ __align__(16) __nv_bfloat16 g_wqt_h[(size_t)DMODEL * DMODEL];
__device__ __align__(16) __nv_bfloat16 g_wqt_l[(size_t)DMODEL * DMODEL];
__device__ __align__(16) __nv_bfloat16 g_wkt_h[(size_t)(NKV*HDIM) * DMODEL];
__device__ __align__(16) __nv_bfloat16 g_wkt_l[(size_t)(NKV*HDIM) * DMODEL];
__device__ __align__(16) __nv_bfloat16 g_wvt_h[(size_t)(NKV*HDIM) * DMODEL];
__device__ __align__(16) __nv_bfloat16 g_wvt_l[(size_t)(NKV*HDIM) * DMODEL];
__device__ __align__(16) __nv_bfloat16 g_wot_h[(size_t)DMODEL * DMODEL];
__device__ __align__(16) __nv_bfloat16 g_wot_l[(size_t)DMODEL * DMODEL];
__device__ __align__(16) __nv_bfloat16 g_oh[(size_t)MROWS * DMODEL];
__device__ __align__(16) __nv_bfloat16 g_ol[(size_t)MROWS * DMODEL];

// ---------------- helpers ---------------------------------------------------
__device__ __forceinline__ uint32_t smem_u32(const void* p) {
    return (uint32_t)__cvta_generic_to_shared(p);
}
__device__ __forceinline__ void cp16(uint32_t dst, const void* src) {
    asm volatile("cp.async.ca.shared.global [%0], [%1], 16;" :: "r"(dst), "l"(src) : "memory");
}
__device__ __forceinline__ void cp_commit() {
    asm volatile("cp.async.commit_group;" ::: "memory");
}
__device__ __forceinline__ void ldsm4(uint32_t& r0, uint32_t& r1, uint32_t& r2, uint32_t& r3,
                                      uint32_t addr) {
    asm volatile("ldmatrix.sync.aligned.m8n8.x4.shared.b16 {%0,%1,%2,%3}, [%4];"
                 : "=r"(r0), "=r"(r1), "=r"(r2), "=r"(r3) : "r"(addr));
}
__device__ __forceinline__ void ldsm4t(uint32_t& r0, uint32_t& r1, uint32_t& r2, uint32_t& r3,
                                       uint32_t addr) {
    asm volatile("ldmatrix.sync.aligned.m8n8.x4.trans.shared.b16 {%0,%1,%2,%3}, [%4];"
                 : "=r"(r0), "=r"(r1), "=r"(r2), "=r"(r3) : "r"(addr));
}
__device__ __forceinline__ void mma_bf16(float* d, const uint32_t* a, const uint32_t* b) {
    asm volatile("mma.sync.aligned.m16n8k16.row.col.f32.bf16.bf16.f32 "
                 "{%0,%1,%2,%3}, {%4,%5,%6,%7}, {%8,%9}, {%0,%1,%2,%3};"
                 : "+f"(d[0]), "+f"(d[1]), "+f"(d[2]), "+f"(d[3])
                 : "r"(a[0]), "r"(a[1]), "r"(a[2]), "r"(a[3]), "r"(b[0]), "r"(b[1]));
}
__device__ __forceinline__ uint32_t packbf(float lo, float hi) {
    uint32_t r;
    asm("cvt.rn.bf16x2.f32 %0, %1, %2;" : "=r"(r) : "f"(hi), "f"(lo));
    return r;
}
__device__ __forceinline__ float fexp2(float x) {
    float r;
    asm("ex2.approx.f32 %0, %1;" : "=f"(r) : "f"(x));
    return r;
}

// ---------------------------------------------------------------------------
// fp32 -> (hi, lo) bf16 split, elementwise
// ---------------------------------------------------------------------------
__global__ void split4_kernel(const float* __restrict__ in,
                              __nv_bfloat16* __restrict__ h,
                              __nv_bfloat16* __restrict__ l, int n4)
{
    int i = blockIdx.x * blockDim.x + threadIdx.x;
    if (i >= n4) return;
    float4 x = ((const float4*)in)[i];
    __nv_bfloat16 h0 = __float2bfloat16(x.x), h1 = __float2bfloat16(x.y);
    __nv_bfloat16 h2 = __float2bfloat16(x.z), h3 = __float2bfloat16(x.w);
    __nv_bfloat16 l0 = __float2bfloat16(x.x - __bfloat162float(h0));
    __nv_bfloat16 l1 = __float2bfloat16(x.y - __bfloat162float(h1));
    __nv_bfloat16 l2 = __float2bfloat16(x.z - __bfloat162float(h2));
    __nv_bfloat16 l3 = __float2bfloat16(x.w - __bfloat162float(h3));
    ((__nv_bfloat162*)h)[2*i]   = __nv_bfloat162(h0, h1);
    ((__nv_bfloat162*)h)[2*i+1] = __nv_bfloat162(h2, h3);
    ((__nv_bfloat162*)l)[2*i]   = __nv_bfloat162(l0, l1);
    ((__nv_bfloat162*)l)[2*i+1] = __nv_bfloat162(l2, l3);
}

// ---------------------------------------------------------------------------
// RoPE + prescale + split: rotate fp32 pairs, scale, emit bf16 hi/lo
// ---------------------------------------------------------------------------
__global__ void rope_split_kernel(const float* __restrict__ src,
                                  const float* __restrict__ cs, const float* __restrict__ sn,
                                  __nv_bfloat16* __restrict__ dh, __nv_bfloat16* __restrict__ dl,
                                  int nheads, int total, float prescale)
{
    int idx = blockIdx.x * blockDim.x + threadIdx.x;
    if (idx >= total) return;
    int p    = idx & 63;
    int rest = idx >> 6;
    int s    = (rest / nheads) & (S_LEN - 1);
    float c  = cs[s * 64 + p];
    float sv = sn[s * 64 + p];
    size_t off = (size_t)rest * HDIM + 2 * p;
    float2 x = *(const float2*)&src[off];
    float o0 = (x.x * c  - x.y * sv) * prescale;
    float o1 = (x.x * sv + x.y * c) * prescale;
    __nv_bfloat16 h0 = __float2bfloat16(o0), h1 = __float2bfloat16(o1);
    *(__nv_bfloat162*)&dh[off] = __nv_bfloat162(h0, h1);
    *(__nv_bfloat162*)&dl[off] = __nv_bfloat162(
        __float2bfloat16(o0 - __bfloat162float(h0)),
        __float2bfloat16(o1 - __bfloat162float(h1)));
}

// ---------------------------------------------------------------------------
// W[K,N] fp32 -> WT[N,K] (hi, lo) bf16, tiled transpose
// ---------------------------------------------------------------------------
__global__ void split_transpose_kernel(const float* __restrict__ W,
                                       __nv_bfloat16* __restrict__ Th,
                                       __nv_bfloat16* __restrict__ Tl,
                                       int K, int N)
{
    __shared__ float t[32][33];
    int k0 = blockIdx.y * 32, n0 = blockIdx.x * 32;
    int x = threadIdx.x, y = threadIdx.y;
#pragma unroll
    for (int j = 0; j < 32; j += 8)
        t[y + j][x] = W[(size_t)(k0 + y + j) * N + n0 + x];
    __syncthreads();
#pragma unroll
    for (int j = 0; j < 32; j += 8) {
        float v = t[x][y + j];
        __nv_bfloat16 h = __float2bfloat16(v);
        __nv_bfloat16 l = __float2bfloat16(v - __bfloat162float(h));
        size_t off = (size_t)(n0 + y + j) * K + k0 + x;
        Th[off] = h;
        Tl[off] = l;
    }
}

// ---------------------------------------------------------------------------
// mma.sync bf16 3-pass GEMM v3: C[M,Ndim] = A[M,K] @ Bt[Ndim,K]^T
// CTA 128x128, BK=32, 8 warps (2x4, warp 64x32), 3-stage cp.async pipeline,
// XOR-swizzled smem (no padding), ONE __syncthreads per iter, 2 CTAs/SM.
// Swizzle: 16B-chunk' = chunk ^ ((row>>1)&3); rows are 64B (32 halves).
// ---------------------------------------------------------------------------
#define ARR8K  (128 * 64)                 // one array: 128 rows x 64B = 8192
#define ST_BYTES (4 * ARR8K)              // Ah,Al,Bh,Bl = 32768
#define O_AH 0
#define O_AL ARR8K
#define O_BH (2 * ARR8K)
#define O_BL (3 * ARR8K)
#define GEMM_SMEM (3 * ST_BYTES)          // 98304

__global__ __launch_bounds__(256, 2) void gemm_mma_bf16x3(
    const __nv_bfloat16* __restrict__ Ah_, const __nv_bfloat16* __restrict__ Al_,
    const __nv_bfloat16* __restrict__ Bh_, const __nv_bfloat16* __restrict__ Bl_,
    float* __restrict__ C, int Ndim, int Kdim)
{
    extern __shared__ __align__(16) char sm[];
    const uint32_t sbase = smem_u32(sm);
    const int tid  = threadIdx.x;
    const int lane = tid & 31;
    const int wid  = tid >> 5;
    const int wm   = wid >> 2;      // 0..1
    const int wn   = wid & 3;       // 0..3
    const int row0 = blockIdx.y * 128;
    const int col0 = blockIdx.x * 128;

    // ---- per-thread cp.async slots: v = tid, tid+256 over 512 slots/array ----
    const int rS0 = tid >> 2,          cS0 = tid & 3;
    const int rS1 = (tid + 256) >> 2,  cS1 = (tid + 256) & 3;
    const uint32_t s0 = (uint32_t)rS0 * 64 + ((cS0 ^ ((rS0 >> 1) & 3)) * 16);
    const uint32_t s1 = (uint32_t)rS1 * 64 + ((cS1 ^ ((rS1 >> 1) & 3)) * 16);
    const char* pAh = (const char*)Ah_;
    const char* pAl = (const char*)Al_;
    const char* pBh = (const char*)Bh_;
    const char* pBl = (const char*)Bl_;
    const size_t gA0 = ((size_t)(row0 + rS0) * Kdim + cS0 * 8) * 2;
    const size_t gA1 = ((size_t)(row0 + rS1) * Kdim + cS1 * 8) * 2;
    const size_t gB0 = ((size_t)(col0 + rS0) * Kdim + cS0 * 8) * 2;
    const size_t gB1 = ((size_t)(col0 + rS1) * Kdim + cS1 * 8) * 2;

    auto stage_cp = [&](int s, int buf) {
        const uint32_t nb = sbase + (uint32_t)buf * ST_BYTES;
        const size_t kb = (size_t)s * 64;
        cp16(nb + O_AH + s0, pAh + gA0 + kb);
        cp16(nb + O_AH + s1, pAh + gA1 + kb);
        cp16(nb + O_AL + s0, pAl + gA0 + kb);
        cp16(nb + O_AL + s1, pAl + gA1 + kb);
        cp16(nb + O_BH + s0, pBh + gB0 + kb);
        cp16(nb + O_BH + s1, pBh + gB1 + kb);
        cp16(nb + O_BL + s0, pBl + gB0 + kb);
        cp16(nb + O_BL + s1, pBl + gB1 + kb);
        cp_commit();
    };

    // ---- ldmatrix addresses (relative to stage base), ks=1 via ^32 ----
    uint32_t aAdr[4], bAdr[2];
    {
        const int ra = wm * 64 + (lane & 15);
        const int ca = lane >> 4;                 // chunk 0/1 within k16
#pragma unroll
        for (int mt = 0; mt < 4; mt++) {
            int r = ra + mt * 16;
            aAdr[mt] = O_AH + (uint32_t)r * 64 + ((ca ^ ((r >> 1) & 3)) * 16);
        }
        const int rb = wn * 32 + ((lane >> 4) << 3) + (lane & 7);
        const int cb = (lane >> 3) & 1;
#pragma unroll
        for (int np = 0; np < 2; np++) {
            int r = rb + np * 16;
            bAdr[np] = O_BH + (uint32_t)r * 64 + ((cb ^ ((r >> 1) & 3)) * 16);
        }
    }

    float acc[4][4][4];
#pragma unroll
    for (int mt = 0; mt < 4; mt++)
#pragma unroll
        for (int nt = 0; nt < 4; nt++)
#pragma unroll
            for (int r = 0; r < 4; r++) acc[mt][nt][r] = 0.0f;

    const int NC = Kdim / 32;     // 128

    // prologue: stages 0 and 1
    stage_cp(0, 0);
    stage_cp(1, 1);

    int buf = 0;
    for (int i = 0; i < NC; i++) {
        if (i + 2 < NC) {
            asm volatile("cp.async.wait_group 1;" ::: "memory");
        } else {
            asm volatile("cp.async.wait_group 0;" ::: "memory");
        }
        __syncthreads();   // stage i visible to all; also releases buf (i+2)%3 for refill

        if (i + 2 < NC) {
            int nb = buf + 2; if (nb >= 3) nb -= 3;
            stage_cp(i + 2, nb);
        }

        const uint32_t st = sbase + (uint32_t)buf * ST_BYTES;
#pragma unroll
        for (int ks = 0; ks < 2; ks++) {
            const uint32_t kx = ks << 5;     // ^32 selects upper k16
            uint32_t ah[4][4], al[4][4], bh[4][2], bl[4][2];
#pragma unroll
            for (int mt = 0; mt < 4; mt++) {
                uint32_t a = st + (aAdr[mt] ^ kx);
                ldsm4(ah[mt][0], ah[mt][1], ah[mt][2], ah[mt][3], a);
                ldsm4(al[mt][0], al[mt][1], al[mt][2], al[mt][3], a + ARR8K);
            }
#pragma unroll
            for (int np = 0; np < 2; np++) {
                uint32_t a = st + (bAdr[np] ^ kx);
                ldsm4(bh[np*2][0], bh[np*2][1], bh[np*2+1][0], bh[np*2+1][1], a);
                ldsm4(bl[np*2][0], bl[np*2][1], bl[np*2+1][0], bl[np*2+1][1], a + ARR8K);
            }
#pragma unroll
            for (int mt = 0; mt < 4; mt++)
#pragma unroll
                for (int nt = 0; nt < 4; nt++) {
                    mma_bf16(acc[mt][nt], ah[mt], bh[nt]);
                    mma_bf16(acc[mt][nt], ah[mt], bl[nt]);
                    mma_bf16(acc[mt][nt], al[mt], bh[nt]);
                }
        }
        if (++buf == 3) buf = 0;
    }

    // epilogue
#pragma unroll
    for (int mt = 0; mt < 4; mt++) {
        int r = row0 + wm * 64 + mt * 16 + (lane >> 2);
#pragma unroll
        for (int nt = 0; nt < 4; nt++) {
            int c = col0 + wn * 32 + nt * 8 + (lane & 3) * 2;
            *(float2*)&C[(size_t)r * Ndim + c]       = make_float2(acc[mt][nt][0], acc[mt][nt][1]);
            *(float2*)&C[(size_t)(r + 8) * Ndim + c] = make_float2(acc[mt][nt][2], acc[mt][nt][3]);
        }
    }
}

// ---------------------------------------------------------------------------
// Tensor-core causal flash attention. Q pre-scaled by (1/sqrt(128))*log2(e),
// so softmax uses exp2 directly (ex2.approx, 1 MUFU per element).
// ---------------------------------------------------------------------------
#define FBR 64
#define FBC 64
#define FP  136
#define FAB (FBR * FP)
#define FLASH2_SMEM (6 * FAB * 2)

__global__ __launch_bounds__(128) void flash_tc(
    const __nv_bfloat16* __restrict__ Qh_, const __nv_bfloat16* __restrict__ Ql_,
    const __nv_bfloat16* __restrict__ Kh_, const __nv_bfloat16* __restrict__ Kl_,
    const __nv_bfloat16* __restrict__ Vh_, const __nv_bfloat16* __restrict__ Vl_,
    __nv_bfloat16* __restrict__ Oh_, __nv_bfloat16* __restrict__ Ol_)
{
    extern __shared__ __align__(16) __nv_bfloat16 smh[];
    const int tid  = threadIdx.x;
    const int lane = tid & 31;
    const int w    = tid >> 5;
    const int qt   = gridDim.x - 1 - blockIdx.x;
    const int h    = blockIdx.y;
    const int b    = blockIdx.z;
    const int g    = h >> 2;
    const int q0   = qt * FBR;

    const uint32_t sb = smem_u32(smh);
    const uint32_t oQh = 0, oKh = 4*FAB, oVh = 8*FAB;

    for (int i = tid; i < FBR * 16; i += 128) {
        int r = i >> 4, c = i & 15;
        size_t gq = ((size_t)((b*S_LEN + q0 + r) * NH) + h) * HDIM + c * 8;
        *(uint4*)&smh[r*FP + c*8]        = *(const uint4*)&Qh_[gq];
        *(uint4*)&smh[FAB + r*FP + c*8]  = *(const uint4*)&Ql_[gq];
    }

    const uint32_t aoff = ((uint32_t)(w*16 + (lane & 15)) * FP) * 2 + (lane >> 4) * 16;
    const uint32_t boff = ((uint32_t)((lane >> 4) * 8 + (lane & 7)) * FP) * 2 + ((lane >> 3) & 1) * 16;
    const uint32_t voff = ((uint32_t)(((lane >> 3) & 1) * 8 + (lane & 7)) * FP) * 2 + (lane >> 4) * 16;

    float oacc[16][4];
#pragma unroll
    for (int t = 0; t < 16; t++)
#pragma unroll
        for (int r = 0; r < 4; r++) oacc[t][r] = 0.0f;
    float m0 = -3.0e38f, m1 = -3.0e38f, l0 = 0.0f, l1 = 0.0f;

    for (int jt = 0; jt <= qt; jt++) {
        const int j0 = jt * FBC;
        __syncthreads();
        for (int i = tid; i < FBC * 16; i += 128) {
            int r = i >> 4, c = i & 15;
            size_t gk = ((size_t)((b*S_LEN + j0 + r) * NKV) + g) * HDIM + c * 8;
            *(uint4*)&smh[2*FAB + r*FP + c*8] = *(const uint4*)&Kh_[gk];
            *(uint4*)&smh[3*FAB + r*FP + c*8] = *(const uint4*)&Kl_[gk];
            *(uint4*)&smh[4*FAB + r*FP + c*8] = *(const uint4*)&Vh_[gk];
            *(uint4*)&smh[5*FAB + r*FP + c*8] = *(const uint4*)&Vl_[gk];
        }
        __syncthreads();

        float sv[8][4];
#pragma unroll
        for (int t = 0; t < 8; t++)
#pragma unroll
            for (int r = 0; r < 4; r++) sv[t][r] = 0.0f;

#pragma unroll
        for (int ks = 0; ks < 8; ks++) {
            uint32_t ah[4], al[4], bh[8][2], bl[8][2];
            ldsm4(ah[0], ah[1], ah[2], ah[3], sb + oQh + aoff + ks*32);
            ldsm4(al[0], al[1], al[2], al[3], sb + oQh + FAB*2 + aoff + ks*32);
#pragma unroll
            for (int nn = 0; nn < 4; nn++) {
                uint32_t adr = sb + oKh + boff + nn * (16*FP*2) + ks*32;
                ldsm4(bh[2*nn][0], bh[2*nn][1], bh[2*nn+1][0], bh[2*nn+1][1], adr);
                ldsm4(bl[2*nn][0], bl[2*nn][1], bl[2*nn+1][0], bl[2*nn+1][1], adr + 2*FAB);
            }
#pragma unroll
            for (int t = 0; t < 8; t++) {
                mma_bf16(sv[t], ah, bh[t]);
                mma_bf16(sv[t], ah, bl[t]);
                mma_bf16(sv[t], al, bh[t]);
            }
        }

        // causal mask only (scores already in log2 domain via pre-scaled Q)
        if (jt == qt) {
            int row = q0 + w*16 + (lane >> 2);
            int cb  = j0 + (lane & 3) * 2;
#pragma unroll
            for (int t = 0; t < 8; t++) {
                int c0 = cb + t*8;
                if (c0     > row    ) sv[t][0] = -1.0e30f;
                if (c0 + 1 > row    ) sv[t][1] = -1.0e30f;
                if (c0     > row + 8) sv[t][2] = -1.0e30f;
                if (c0 + 1 > row + 8) sv[t][3] = -1.0e30f;
            }
        }

        float mx0 = -1.0e30f, mx1 = -1.0e30f;
#pragma unroll
        for (int t = 0; t < 8; t++) {
            mx0 = fmaxf(mx0, fmaxf(sv[t][0], sv[t][1]));
            mx1 = fmaxf(mx1, fmaxf(sv[t][2], sv[t][3]));
        }
        mx0 = fmaxf(mx0, __shfl_xor_sync(0xffffffffu, mx0, 1));
        mx0 = fmaxf(mx0, __shfl_xor_sync(0xffffffffu, mx0, 2));
        mx1 = fmaxf(mx1, __shfl_xor_sync(0xffffffffu, mx1, 1));
        mx1 = fmaxf(mx1, __shfl_xor_sync(0xffffffffu, mx1, 2));
        float mnew0 = fmaxf(m0, mx0), mnew1 = fmaxf(m1, mx1);
        float corr0 = fexp2(m0 - mnew0), corr1 = fexp2(m1 - mnew1);

        float rl0 = 0.0f, rl1 = 0.0f;
        uint32_t paH[4][4], paL[4][4];
#pragma unroll
        for (int u = 0; u < 4; u++) {
            float p00 = fexp2(sv[2*u][0]   - mnew0), p01 = fexp2(sv[2*u][1]   - mnew0);
            float p02 = fexp2(sv[2*u][2]   - mnew1), p03 = fexp2(sv[2*u][3]   - mnew1);
            float p10 = fexp2(sv[2*u+1][0] - mnew0), p11 = fexp2(sv[2*u+1][1] - mnew0);
            float p12 = fexp2(sv[2*u+1][2] - mnew1), p13 = fexp2(sv[2*u+1][3] - mnew1);
            rl0 += p00 + p01 + p10 + p11;
            rl1 += p02 + p03 + p12 + p13;
            paH[u][0] = packbf(p00, p01);
            paH[u][1] = packbf(p02, p03);
            paH[u][2] = packbf(p10, p11);
            paH[u][3] = packbf(p12, p13);
            float q00 = p00 - __bfloat162float(__float2bfloat16(p00));
            float q01 = p01 - __bfloat162float(__float2bfloat16(p01));
            float q02 = p02 - __bfloat162float(__float2bfloat16(p02));
            float q03 = p03 - __bfloat162float(__float2bfloat16(p03));
            float q10 = p10 - __bfloat162float(__float2bfloat16(p10));
            float q11 = p11 - __bfloat162float(__float2bfloat16(p11));
            float q12 = p12 - __bfloat162float(__float2bfloat16(p12));
            float q13 = p13 - __bfloat162float(__float2bfloat16(p13));
            paL[u][0] = packbf(q00, q01);
            paL[u][1] = packbf(q02, q03);
            paL[u][2] = packbf(q10, q11);
            paL[u][3] = packbf(q12, q13);
        }
        rl0 += __shfl_xor_sync(0xffffffffu, rl0, 1);
        rl0 += __shfl_xor_sync(0xffffffffu, rl0, 2);
        rl1 += __shfl_xor_sync(0xffffffffu, rl1, 1);
        rl1 += __shfl_xor_sync(0xffffffffu, rl1, 2);
        l0 = l0 * corr0 + rl0;
        l1 = l1 * corr1 + rl1;
        m0 = mnew0; m1 = mnew1;
#pragma unroll
        for (int t = 0; t < 16; t++) {
            oacc[t][0] *= corr0; oacc[t][1] *= corr0;
            oacc[t][2] *= corr1; oacc[t][3] *= corr1;
        }

#pragma unroll
        for (int u = 0; u < 4; u++) {
#pragma unroll
            for (int dh2 = 0; dh2 < 2; dh2++) {
                uint32_t bvh[8][2], bvl[8][2];
#pragma unroll
                for (int dd = 0; dd < 4; dd++) {
                    uint32_t adr = sb + oVh + voff + u * (16*FP*2) + (dh2*64 + dd*16) * 2;
                    ldsm4t(bvh[2*dd][0], bvh[2*dd][1], bvh[2*dd+1][0], bvh[2*dd+1][1], adr);
                    ldsm4t(bvl[2*dd][0], bvl[2*dd][1], bvl[2*dd+1][0], bvl[2*dd+1][1], adr + 2*FAB);
                }
#pragma unroll
                for (int t = 0; t < 8; t++) {
                    mma_bf16(oacc[dh2*8+t], paH[u], bvh[t]);
                    mma_bf16(oacc[dh2*8+t], paH[u], bvl[t]);
                    mma_bf16(oacc[dh2*8+t], paL[u], bvh[t]);
                }
            }
        }
    }

    float inv0 = 1.0f / l0, inv1 = 1.0f / l1;
    int rowa = b*S_LEN + q0 + w*16 + (lane >> 2);
    size_t base0 = ((size_t)rowa * NH + h) * HDIM;
    size_t base1 = base0 + (size_t)8 * NH * HDIM;
#pragma unroll
    for (int t = 0; t < 16; t++) {
        int c = t*8 + (lane & 3) * 2;
        float v0 = oacc[t][0] * inv0, v1 = oacc[t][1] * inv0;
        float v2 = oacc[t][2] * inv1, v3 = oacc[t][3] * inv1;
        __nv_bfloat16 h0 = __float2bfloat16(v0), h1 = __float2bfloat16(v1);
        __nv_bfloat16 h2 = __float2bfloat16(v2), h3 = __float2bfloat16(v3);
        *(__nv_bfloat162*)&Oh_[base0 + c] = __nv_bfloat162(h0, h1);
        *(__nv_bfloat162*)&Oh_[base1 + c] = __nv_bfloat162(h2, h3);
        *(__nv_bfloat162*)&Ol_[base0 + c] = __nv_bfloat162(
            __float2bfloat16(v0 - __bfloat162float(h0)),
            __float2bfloat16(v1 - __bfloat162float(h1)));
        *(__nv_bfloat162*)&Ol_[base1 + c] = __nv_bfloat162(
            __float2bfloat16(v2 - __bfloat162float(h2)),
            __float2bfloat16(v3 - __bfloat162float(h3)));
    }
}

// ---------------------------------------------------------------------------
// Launch
// ---------------------------------------------------------------------------
extern "C" void kernel_launch(void* const* d_in, const int* in_sizes, int n_in,
                              void* d_out, int out_size)
{
    const float* x  = (const float*)d_in[0];
    const float* wq = (const float*)d_in[1];
    const float* wk = (const float*)d_in[2];
    const float* wv = (const float*)d_in[3];
    const float* wo = (const float*)d_in[4];
    const float* fc = (const float*)d_in[5];
    const float* fs = (const float*)d_in[6];
    float* out = (float*)d_out;

    float *q, *k, *v;
    cudaGetSymbolAddress((void**)&q, g_q);
    cudaGetSymbolAddress((void**)&k, g_k);
    cudaGetSymbolAddress((void**)&v, g_v);
    __nv_bfloat16 *xh, *xl, *kh, *kl, *vh, *vl;
    __nv_bfloat16 *wqth, *wqtl, *wkth, *wktl, *wvth, *wvtl, *woth, *wotl, *oh, *ol;
    cudaGetSymbolAddress((void**)&xh, g_xh);      cudaGetSymbolAddress((void**)&xl, g_xl);
    cudaGetSymbolAddress((void**)&kh, g_kh);      cudaGetSymbolAddress((void**)&kl, g_kl);
    cudaGetSymbolAddress((void**)&vh, g_vh);      cudaGetSymbolAddress((void**)&vl, g_vl);
    cudaGetSymbolAddress((void**)&wqth, g_wqt_h); cudaGetSymbolAddress((void**)&wqtl, g_wqt_l);
    cudaGetSymbolAddress((void**)&wkth, g_wkt_h); cudaGetSymbolAddress((void**)&wktl, g_wkt_l);
    cudaGetSymbolAddress((void**)&wvth, g_wvt_h); cudaGetSymbolAddress((void**)&wvtl, g_wvt_l);
    cudaGetSymbolAddress((void**)&woth, g_wot_h); cudaGetSymbolAddress((void**)&wotl, g_wot_l);
    cudaGetSymbolAddress((void**)&oh, g_oh);      cudaGetSymbolAddress((void**)&ol, g_ol);

    // split inputs / weights into bf16 hi/lo
    int n4 = (MROWS * DMODEL) / 4;
    split4_kernel<<<(n4 + 255) / 256, 256>>>(x, xh, xl, n4);
    split_transpose_kernel<<<dim3(DMODEL / 32, DMODEL / 32), dim3(32, 8)>>>(wq, wqth, wqtl, DMODEL, DMODEL);
    split_transpose_kernel<<<dim3((NKV * HDIM) / 32, DMODEL / 32), dim3(32, 8)>>>(wk, wkth, wktl, DMODEL, NKV * HDIM);
    split_transpose_kernel<<<dim3((NKV * HDIM) / 32, DMODEL / 32), dim3(32, 8)>>>(wv, wvth, wvtl, DMODEL, NKV * HDIM);
    split_transpose_kernel<<<dim3(DMODEL / 32, DMODEL / 32), dim3(32, 8)>>>(wo, woth, wotl, DMODEL, DMODEL);

    cudaFuncSetAttribute(gemm_mma_bf16x3, cudaFuncAttributeMaxDynamicSharedMemorySize, GEMM_SMEM);

    // QKV projections
    gemm_mma_bf16x3<<<dim3((NH * HDIM) / 128,  MROWS / 128), 256, GEMM_SMEM>>>(xh, xl, wqth, wqtl, q, NH * HDIM,  DMODEL);
    gemm_mma_bf16x3<<<dim3((NKV * HDIM) / 128, MROWS / 128), 256, GEMM_SMEM>>>(xh, xl, wkth, wktl, k, NKV * HDIM, DMODEL);
    gemm_mma_bf16x3<<<dim3((NKV * HDIM) / 128, MROWS / 128), 256, GEMM_SMEM>>>(xh, xl, wvth, wvtl, v, NKV * HDIM, DMODEL);

    // RoPE + bf16 split; Q pre-scaled by 1/sqrt(HD) * log2(e) for exp2 softmax
    const float qscale = 0.08838834764831845f * 1.4426950408889634f;
    int qtot = MROWS * NH  * 64;
    int ktot = MROWS * NKV * 64;
    rope_split_kernel<<<(qtot + 255) / 256, 256>>>(q, fc, fs, xh, xl, NH,  qtot, qscale);
    rope_split_kernel<<<(ktot + 255) / 256, 256>>>(k, fc, fs, kh, kl, NKV, ktot, 1.0f);
    int v4 = (MROWS * NKV * HDIM) / 4;
    split4_kernel<<<(v4 + 255) / 256, 256>>>(v, vh, vl, v4);

    // Tensor-core flash attention -> bf16 hi/lo output
    cudaFuncSetAttribute(flash_tc, cudaFuncAttributeMaxDynamicSharedMemorySize, FLASH2_SMEM);
    flash_tc<<<dim3(S_LEN / FBR, NH, BATCH), 128, FLASH2_SMEM>>>(xh, xl, kh, kl, vh, vl, oh, ol);

    // Output projection
    gemm_mma_bf16x3<<<dim3(DMODEL / 128, MROWS / 128), 256, GEMM_SMEM>>>(oh, ol, woth, wotl, out, DMODEL, DMODEL);
}